// round 6
// baseline (speedup 1.0000x reference)
#include <cuda_runtime.h>
#include <cuda_bf16.h>
#include <math.h>
#include <cstdint>

// Stickbreaking attention, B=1, H=16, S=2048, Dh=64, fp32.
//
// fp32-faithful structure:
//  (1) Mask(-1e9)-before-cumsum => every query row except i=S-1 is exactly 0.
//  (2) Row S-1: suffix sums of log_sigmoid(-l) are monotone non-increasing;
//      once carry < -120, expf == 0.0f exactly for all remaining keys.
//
// Grid = 148, one wave. Blocks 0..15: one head each; single cp.async front
// (K+V+q), swizzled K SMEM, register-resident q, redundant warp-offset scan,
// flat 1-sync reduction. Blocks 16..147: zero the output.

#define SB_H  16
#define SB_S  2048
#define SB_D  64
#define SB_SCALE 0.125f
#define SB_CHUNK 256
#define SB_NBLK  148
#define SB_CUTOFF -120.0f

// dynamic smem layout (bytes)
#define OFF_Q     0            // float4[16]  (q row staging)
#define OFF_WS8   256          // float[8]    (warp totals)
#define OFF_WSM   1024         // float[256]  (weights, t-indexed)
#define OFF_K     2048         // float4[4096] = 64 KB (XOR-swizzled rows)
#define OFF_V     (2048 + 65536)   // float4[4096] = 64 KB (identity layout)
#define SB_SMEM   (2048 + 65536 + 65536)

__global__ __launch_bounds__(512, 1)
void sb_fused_kernel(const float* __restrict__ q,
                     const float* __restrict__ k,
                     const float* __restrict__ v,
                     float* __restrict__ out) {
    const int bid = blockIdx.x;
    const int tid = threadIdx.x;

    if (bid >= SB_H) {
        // ---------------- zero path ----------------
        float4* o4 = reinterpret_cast<float4*>(out);
        const int total4 = SB_H * SB_S * SB_D / 4;     // 524288
        const int per_head4 = SB_S * SB_D / 4;         // 32768
        const int stride = (SB_NBLK - SB_H) * 512;
        const float4 z4 = make_float4(0.f, 0.f, 0.f, 0.f);
        for (int i = (bid - SB_H) * 512 + tid; i < total4; i += stride) {
            if ((i & (per_head4 - 1)) < per_head4 - (SB_D / 4))
                o4[i] = z4;
        }
        return;
    }

    // ---------------- compute path: head h = bid ----------------
    extern __shared__ char smem[];
    float4* q_sm = reinterpret_cast<float4*>(smem + OFF_Q);
    float*  ws8  = reinterpret_cast<float*>(smem + OFF_WS8);
    float*  wsm  = reinterpret_cast<float*>(smem + OFF_WSM);
    float4* k_sm = reinterpret_cast<float4*>(smem + OFF_K);
    float4* v_sm = reinterpret_cast<float4*>(smem + OFF_V);
    float4* red4 = reinterpret_cast<float4*>(smem + OFF_K);   // alias K (dead by reduce)

    const unsigned int q_sm_u = (unsigned int)__cvta_generic_to_shared(q_sm);
    const unsigned int k_sm_u = (unsigned int)__cvta_generic_to_shared(k_sm);
    const unsigned int v_sm_u = (unsigned int)__cvta_generic_to_shared(v_sm);

    const int h    = bid;
    const int lane = tid & 31;
    const int wid  = tid >> 5;

    const size_t head_base = (size_t)h * SB_S * SB_D;
    const float4* q4 = reinterpret_cast<const float4*>(q + head_base + (size_t)(SB_S - 1) * SB_D);
    const float4* k4 = reinterpret_cast<const float4*>(k + head_base);
    const float4* v4 = reinterpret_cast<const float4*>(v + head_base);

    const int kg = tid >> 4;      // 0..31 matvec key-group (8 keys)
    const int d4 = tid & 15;      // 0..15 float4 dim slot
    float4 acc = make_float4(0.f, 0.f, 0.f, 0.f);
    float carry = 0.f;
    float4 qr[16];                // q row in registers (loaded once)

    for (int c = 0; c < SB_S / SB_CHUNK; c++) {
        const int jb = SB_S - (c + 1) * SB_CHUNK;      // first global row of chunk
        const float4* kb4 = k4 + (size_t)jb * 16;
        const float4* vb4 = v4 + (size_t)jb * 16;

        // ---- single cp.async front: K (swizzled), V (identity), q (c==0) ----
        #pragma unroll
        for (int u = 0; u < 8; u++) {
            const int g  = u * 512 + tid;              // 0..4095, source-linear
            const int rv = g >> 4;                     // row in chunk
            const int dd = g & 15;
            const unsigned int kd = k_sm_u + (unsigned int)(rv * 16 + ((dd + rv) & 15)) * 16u;
            asm volatile("cp.async.cg.shared.global [%0], [%1], 16;\n"
                         :: "r"(kd), "l"(kb4 + g));
            const unsigned int vd = v_sm_u + (unsigned int)g * 16u;
            asm volatile("cp.async.cg.shared.global [%0], [%1], 16;\n"
                         :: "r"(vd), "l"(vb4 + g));
        }
        if (c == 0 && tid < 16) {
            asm volatile("cp.async.cg.shared.global [%0], [%1], 16;\n"
                         :: "r"(q_sm_u + (unsigned int)tid * 16u), "l"(q4 + tid));
        }
        asm volatile("cp.async.commit_group;\n" ::: "memory");
        asm volatile("cp.async.wait_group 0;\n" ::: "memory");
        __syncthreads();                               // sync0: smem visible

        if (c == 0) {
            #pragma unroll
            for (int i = 0; i < 16; i++) qr[i] = q_sm[i];
        }

        // ---- logits + warp scan (threads 0..255, one key each) ----
        float ws = 0.f, l = 0.f;
        if (tid < SB_CHUNK) {
            const int r = 255 - tid;                   // chunk row (t=tid -> j=jb+r)
            float dot = 0.f;
            #pragma unroll
            for (int i = 0; i < 16; i++) {
                const float4 kv = k_sm[r * 16 + ((i + r) & 15)];
                const float4 qv = qr[i];
                dot += kv.x * qv.x + kv.y * qv.y + kv.z * qv.z + kv.w * qv.w;
            }
            l = dot * SB_SCALE;
            const float p = -(fmaxf(l, 0.f) + log1pf(expf(-fabsf(l))));
            ws = p;
            #pragma unroll
            for (int off = 1; off < 32; off <<= 1) {
                float n = __shfl_up_sync(0xFFFFFFFFu, ws, off);
                if (lane >= off) ws += n;
            }
            if (lane == 31) ws8[wid] = ws;
        }
        __syncthreads();                               // sync1: ws8 visible

        // ---- redundant warp-offset + block total (no extra barrier) ----
        float warp_excl = 0.f, btot = 0.f;
        #pragma unroll
        for (int w = 0; w < 8; w++) {
            const float s = ws8[w];
            btot += s;
            if (w < wid) warp_excl += s;
        }
        if (tid < SB_CHUNK) {
            const float S_t = carry + warp_excl + ws;
            const float z = 1.f / (1.f + expf(-l));
            wsm[tid] = z * expf(S_t);                  // exact 0 on underflow
        }
        __syncthreads();                               // sync2: wsm visible

        // ---- matvec from SMEM: all 512 threads, 8 keys x 1 float4 ----
        #pragma unroll
        for (int u = 0; u < 8; u++) {
            const int tt = kg * 8 + u;                 // t-local key
            const int rv = 255 - tt;                   // chunk row
            const float  w  = wsm[tt];
            const float4 vv = v_sm[rv * 16 + d4];
            acc.x += w * vv.x;
            acc.y += w * vv.y;
            acc.z += w * vv.z;
            acc.w += w * vv.w;
        }

        carry += btot;
        if (carry < SB_CUTOFF) break;                  // remaining weights exactly 0.0f
        __syncthreads();                               // protect smem before next chunk
    }

    // ---- flat reduction: 512 partials -> 16 float4, one barrier pair ----
    __syncthreads();                                   // matvec reads done (alias safety)
    red4[tid] = acc;
    __syncthreads();
    if (tid < 16) {
        float4 s = make_float4(0.f, 0.f, 0.f, 0.f);
        #pragma unroll
        for (int g = 0; g < 32; g++) {
            const float4 b = red4[g * 16 + tid];
            s.x += b.x; s.y += b.y; s.z += b.z; s.w += b.w;
        }
        float4* out4 = reinterpret_cast<float4*>(out + head_base + (size_t)(SB_S - 1) * SB_D);
        out4[tid] = s;
    }
}

extern "C" void kernel_launch(void* const* d_in, const int* in_sizes, int n_in,
                              void* d_out, int out_size) {
    const float* q = (const float*)d_in[0];
    const float* k = (const float*)d_in[1];
    const float* v = (const float*)d_in[2];
    float* out = (float*)d_out;

    static bool attr_set = false;
    if (!attr_set) {
        cudaFuncSetAttribute(sb_fused_kernel,
                             cudaFuncAttributeMaxDynamicSharedMemorySize, SB_SMEM);
        attr_set = true;
    }
    sb_fused_kernel<<<SB_NBLK, 512, SB_SMEM>>>(q, k, v, out);
}

// round 7
// speedup vs baseline: 1.0257x; 1.0257x over previous
#include <cuda_runtime.h>
#include <cuda_bf16.h>
#include <math.h>
#include <cstdint>

// Stickbreaking attention, B=1, H=16, S=2048, Dh=64, fp32.
//
// fp32-faithful structure:
//  (1) Mask(-1e9)-before-cumsum => every query row except i=S-1 is exactly 0.
//  (2) Row S-1: suffix sums of log_sigmoid(-l) are monotone non-increasing;
//      once carry < -120, expf == 0.0f exactly for all remaining keys.
//
// Grid = 148, one wave. Blocks 0..15: one head each. Split cp.async groups
// (K+q first, V second) so the V fill overlaps logits+scan; 2 threads/key
// logits (shfl-combined halves); even-lane scan; single-barrier reduction.
// Blocks 16..147: zero the output.

#define SB_H  16
#define SB_S  2048
#define SB_D  64
#define SB_SCALE 0.125f
#define SB_CHUNK 256
#define SB_NBLK  148
#define SB_CUTOFF -120.0f

// dynamic smem layout (bytes)
#define OFF_Q     0                // float4[16]
#define OFF_WS16  256              // float[16] warp totals
#define OFF_WSM   1024             // float[256] weights (key-indexed)
#define OFF_K     2048             // float4[4096] = 64 KB (XOR-swizzled rows)
#define OFF_V     (2048 + 65536)   // float4[4096] = 64 KB
#define SB_SMEM   (2048 + 65536 + 65536)

__global__ __launch_bounds__(512, 1)
void sb_fused_kernel(const float* __restrict__ q,
                     const float* __restrict__ k,
                     const float* __restrict__ v,
                     float* __restrict__ out) {
    const int bid = blockIdx.x;
    const int tid = threadIdx.x;

    if (bid >= SB_H) {
        // ---------------- zero path ----------------
        float4* o4 = reinterpret_cast<float4*>(out);
        const int total4 = SB_H * SB_S * SB_D / 4;     // 524288
        const int per_head4 = SB_S * SB_D / 4;         // 32768
        const int stride = (SB_NBLK - SB_H) * 512;
        const float4 z4 = make_float4(0.f, 0.f, 0.f, 0.f);
        for (int i = (bid - SB_H) * 512 + tid; i < total4; i += stride) {
            if ((i & (per_head4 - 1)) < per_head4 - (SB_D / 4))
                o4[i] = z4;
        }
        return;
    }

    // ---------------- compute path: head h = bid ----------------
    extern __shared__ char smem[];
    float4* q_sm = reinterpret_cast<float4*>(smem + OFF_Q);
    float*  ws16 = reinterpret_cast<float*>(smem + OFF_WS16);
    float*  wsm  = reinterpret_cast<float*>(smem + OFF_WSM);
    float4* k_sm = reinterpret_cast<float4*>(smem + OFF_K);
    float4* v_sm = reinterpret_cast<float4*>(smem + OFF_V);
    float4* red4 = reinterpret_cast<float4*>(smem + OFF_K);   // alias K (dead post-logits)

    const unsigned int q_sm_u = (unsigned int)__cvta_generic_to_shared(q_sm);
    const unsigned int k_sm_u = (unsigned int)__cvta_generic_to_shared(k_sm);
    const unsigned int v_sm_u = (unsigned int)__cvta_generic_to_shared(v_sm);

    const int h    = bid;
    const int lane = tid & 31;
    const int wid  = tid >> 5;                 // 16 warps
    const int hf   = tid & 1;                  // half of the dot product
    const int key  = tid >> 1;                 // 0..255 (scan order t)

    const size_t head_base = (size_t)h * SB_S * SB_D;
    const float4* q4 = reinterpret_cast<const float4*>(q + head_base + (size_t)(SB_S - 1) * SB_D);
    const float4* k4 = reinterpret_cast<const float4*>(k + head_base);
    const float4* v4 = reinterpret_cast<const float4*>(v + head_base);

    const int kg = tid >> 4;                   // matvec key-group (8 keys)
    const int d4 = tid & 15;                   // float4 dim slot
    float4 acc = make_float4(0.f, 0.f, 0.f, 0.f);
    float carry = 0.f;
    float4 qh[8];                              // this thread's half of q

    for (int c = 0; c < SB_S / SB_CHUNK; c++) {
        const int jb = SB_S - (c + 1) * SB_CHUNK;
        const float4* kb4 = k4 + (size_t)jb * 16;
        const float4* vb4 = v4 + (size_t)jb * 16;

        // ---- group 0: q (c==0) + K (swizzled) ----
        if (c == 0 && tid < 16) {
            asm volatile("cp.async.cg.shared.global [%0], [%1], 16;\n"
                         :: "r"(q_sm_u + (unsigned int)tid * 16u), "l"(q4 + tid));
        }
        #pragma unroll
        for (int u = 0; u < 8; u++) {
            const int g  = u * 512 + tid;              // 0..4095
            const int rv = g >> 4;
            const int dd = g & 15;
            const unsigned int kd = k_sm_u + (unsigned int)(rv * 16 + ((dd + rv) & 15)) * 16u;
            asm volatile("cp.async.cg.shared.global [%0], [%1], 16;\n"
                         :: "r"(kd), "l"(kb4 + g));
        }
        asm volatile("cp.async.commit_group;\n" ::: "memory");

        // ---- group 1: V (identity layout) ----
        #pragma unroll
        for (int u = 0; u < 8; u++) {
            const int g = u * 512 + tid;
            asm volatile("cp.async.cg.shared.global [%0], [%1], 16;\n"
                         :: "r"(v_sm_u + (unsigned int)g * 16u), "l"(vb4 + g));
        }
        asm volatile("cp.async.commit_group;\n" ::: "memory");

        // ---- wait for K(+q) only; V keeps streaming ----
        asm volatile("cp.async.wait_group 1;\n" ::: "memory");
        __syncthreads();                               // sync0: K,q visible

        if (c == 0) {
            #pragma unroll
            for (int i = 0; i < 8; i++) qh[i] = q_sm[hf * 8 + i];
        }

        // ---- logits: 2 threads/key, 8 LDS.128 each ----
        const int r = 255 - key;                       // chunk row for this key
        float dot = 0.f;
        #pragma unroll
        for (int i = 0; i < 8; i++) {
            const float4 kv = k_sm[r * 16 + ((i + 8 * hf + r) & 15)];
            const float4 qv = qh[i];
            dot += kv.x * qv.x + kv.y * qv.y + kv.z * qv.z + kv.w * qv.w;
        }
        dot += __shfl_xor_sync(0xFFFFFFFFu, dot, 1);   // combine halves
        const float l = dot * SB_SCALE;
        const float p = -(fmaxf(l, 0.f) + log1pf(expf(-fabsf(l))));

        // ---- inclusive scan over keys: even lanes carry p, odd carry 0 ----
        float ws = hf ? 0.f : p;
        #pragma unroll
        for (int off = 1; off < 32; off <<= 1) {
            float n = __shfl_up_sync(0xFFFFFFFFu, ws, off);
            if (lane >= off) ws += n;
        }
        if (lane == 31) ws16[wid] = ws;
        __syncthreads();                               // sync1: ws16 visible

        float warp_excl = 0.f, btot = 0.f;
        #pragma unroll
        for (int w = 0; w < 16; w++) {
            const float s = ws16[w];
            btot += s;
            if (w < wid) warp_excl += s;
        }
        if (hf == 0) {
            const float S_t = carry + warp_excl + ws;  // inclusive through this key
            const float z = 1.f / (1.f + expf(-l));
            wsm[key] = z * expf(S_t);                  // exact 0 on underflow
        }

        asm volatile("cp.async.wait_group 0;\n" ::: "memory");   // V done
        __syncthreads();                               // sync2: wsm + V visible

        // ---- matvec from SMEM: 512 threads, 8 keys x 1 float4 ----
        #pragma unroll
        for (int u = 0; u < 8; u++) {
            const int tt = kg * 8 + u;                 // key index
            const int rv = 255 - tt;                   // chunk row
            const float  w  = wsm[tt];
            const float4 vv = v_sm[rv * 16 + d4];
            acc.x += w * vv.x;
            acc.y += w * vv.y;
            acc.z += w * vv.z;
            acc.w += w * vv.w;
        }

        carry += btot;
        if (carry < SB_CUTOFF) break;                  // remaining weights exactly 0.0f
        __syncthreads();                               // protect smem before next chunk
    }

    // ---- flat reduction (red4 aliases K region: no readers post-logits) ----
    red4[tid] = acc;
    __syncthreads();
    if (tid < 16) {
        float4 s = make_float4(0.f, 0.f, 0.f, 0.f);
        #pragma unroll
        for (int g = 0; g < 32; g++) {
            const float4 b = red4[g * 16 + tid];
            s.x += b.x; s.y += b.y; s.z += b.z; s.w += b.w;
        }
        float4* out4 = reinterpret_cast<float4*>(out + head_base + (size_t)(SB_S - 1) * SB_D);
        out4[tid] = s;
    }
}

extern "C" void kernel_launch(void* const* d_in, const int* in_sizes, int n_in,
                              void* d_out, int out_size) {
    const float* q = (const float*)d_in[0];
    const float* k = (const float*)d_in[1];
    const float* v = (const float*)d_in[2];
    float* out = (float*)d_out;

    static bool attr_set = false;
    if (!attr_set) {
        cudaFuncSetAttribute(sb_fused_kernel,
                             cudaFuncAttributeMaxDynamicSharedMemorySize, SB_SMEM);
        attr_set = true;
    }
    sb_fused_kernel<<<SB_NBLK, 512, SB_SMEM>>>(q, k, v, out);
}